// round 8
// baseline (speedup 1.0000x reference)
#include <cuda_runtime.h>

using ull = unsigned long long;

// ---------- packed f32x2 + MUFU helpers ----------
__device__ __forceinline__ ull pk2(float lo, float hi) {
    ull r; asm("mov.b64 %0, {%1, %2};" : "=l"(r) : "f"(lo), "f"(hi)); return r;
}
__device__ __forceinline__ void upk2(ull v, float& lo, float& hi) {
    asm("mov.b64 {%0, %1}, %2;" : "=f"(lo), "=f"(hi) : "l"(v));
}
__device__ __forceinline__ ull fma2(ull a, ull b, ull c) {
    ull d; asm("fma.rn.f32x2 %0, %1, %2, %3;" : "=l"(d) : "l"(a), "l"(b), "l"(c)); return d;
}
__device__ __forceinline__ float tanhf_hw(float x) {
    float y; asm("tanh.approx.f32 %0, %1;" : "=f"(y) : "f"(x)); return y;
}

#define HID 10
#define PF  4

// R7 core (smem h-exchange, k-packed dots, 1 MUFU/gate) + TWO independent
// 3-element streams per warp, fully inlined and statement-interleaved so
// ptxas statically overlaps the two dependence chains (ILP-2). Stream A:
// elems wg*6+grp, stream B: wg*6+3+grp. Weights are shared registers.
__global__ void __launch_bounds__(32, 6)
lstm_dual2_kernel(const float* __restrict__ x,
                  const float* __restrict__ w_ih,
                  const float* __restrict__ w_hh,
                  const float* __restrict__ b_ih,
                  const float* __restrict__ b_hh,
                  const float* __restrict__ fc_w,
                  const float* __restrict__ fc_b,
                  float* __restrict__ out,
                  int S, int B)
{
    // [pingpong][stream][grp][16 floats] -> 64B-aligned rows for LDS.128
    __shared__ float hsh[2][2][3][16];

    const int lane = threadIdx.x & 31;
    const int wg   = blockIdx.x;

    int grp = lane / HID; if (grp > 2) grp = 2;            // lanes 30,31 -> grp 2
    int j   = lane - grp * HID; if (j >= HID) j = HID - 1; // dup lanes -> j=9

    int bA = wg * 6 + grp;
    int bB = wg * 6 + 3 + grp;
    const bool liveA = (bA < B) && (lane < 30);
    const bool liveB = (bB < B) && (lane < 30);
    if (bA >= B) bA = B - 1;
    if (bB >= B) bB = B - 1;

    // ---- shared per-lane packed weights over k-pairs ----
    // rows: 0=i(x0.5), 1=f(x0.5), 2=g(x1), 3=o(x0.5)
    ull w2[4][5], wxb[4], bb2[4];
#pragma unroll
    for (int r = 0; r < 4; ++r) {
        const float sc = (r == 2) ? 1.0f : 0.5f;
        const int row = r * HID + j;
#pragma unroll
        for (int p = 0; p < 5; ++p)
            w2[r][p] = pk2(sc * w_hh[row * HID + 2 * p],
                           sc * w_hh[row * HID + 2 * p + 1]);
        wxb[r] = pk2(sc * w_ih[row], 0.f);
        bb2[r] = pk2(sc * (b_ih[row] + b_hh[row]), 0.f);
    }

    ull fc2[5];
#pragma unroll
    for (int p = 0; p < 5; ++p) fc2[p] = pk2(fc_w[2 * p], fc_w[2 * p + 1]);
    const ull fb2 = pk2(fc_b[0], 0.f);

    // ---- per-stream state ----
    ull hA[5], hB[5];
#pragma unroll
    for (int p = 0; p < 5; ++p) { hA[p] = 0ull; hB[p] = 0ull; }
    float cA = 0.f, cB = 0.f;

    // ---- x prefetch pipelines ----
    float xbufA[PF], xbufB[PF];
#pragma unroll
    for (int i = 0; i < PF; ++i) {
        int ti = (i < S) ? i : (S - 1);
        xbufA[i] = __ldg(x + (size_t)ti * B + bA);
        xbufB[i] = __ldg(x + (size_t)ti * B + bB);
    }

    float* opA = out + bA;
    float* opB = out + bB;
    int w = 0;

    for (int t = 0; t < S; t += PF) {
#pragma unroll
        for (int u = 0; u < PF; ++u) {
            const float xtA = xbufA[u];
            const float xtB = xbufB[u];
            int tn = t + u + PF; tn = (tn < S) ? tn : (S - 1);
            xbufA[u] = __ldg(x + (size_t)tn * B + bA);
            xbufB[u] = __ldg(x + (size_t)tn * B + bB);

            const ull xdA = pk2(xtA, xtA);
            const ull xdB = pk2(xtB, xtB);

            // gate dots: both streams interleaved per row
            float sA[4], sB[4];
#pragma unroll
            for (int r = 0; r < 4; ++r) {
                ull aA = fma2(xdA, wxb[r], bb2[r]);
                ull aB = fma2(xdB, wxb[r], bb2[r]);
#pragma unroll
                for (int p = 0; p < 5; ++p) {
                    aA = fma2(hA[p], w2[r][p], aA);
                    aB = fma2(hB[p], w2[r][p], aB);
                }
                float lo, hi;
                upk2(aA, lo, hi); sA[r] = lo + hi;
                upk2(aB, lo, hi); sB[r] = lo + hi;
            }

            // activations, interleaved
            const float iaA = fmaf(0.5f, tanhf_hw(sA[0]), 0.5f);
            const float iaB = fmaf(0.5f, tanhf_hw(sB[0]), 0.5f);
            const float faA = fmaf(0.5f, tanhf_hw(sA[1]), 0.5f);
            const float faB = fmaf(0.5f, tanhf_hw(sB[1]), 0.5f);
            const float gaA = tanhf_hw(sA[2]);
            const float gaB = tanhf_hw(sB[2]);
            const float oaA = fmaf(0.5f, tanhf_hw(sA[3]), 0.5f);
            const float oaB = fmaf(0.5f, tanhf_hw(sB[3]), 0.5f);

            const float cnA = fmaf(iaA, gaA, faA * cA);
            const float cnB = fmaf(iaB, gaB, faB * cB);
            cA = cnA;
            cB = cnB;
            const float hnA = oaA * tanhf_hw(cnA);
            const float hnB = oaB * tanhf_hw(cnB);

            // ---- h exchange (both streams share one syncwarp) ----
            hsh[w][0][grp][j] = hnA;
            hsh[w][1][grp][j] = hnB;
            __syncwarp();
            {
                const float4 a0 = *(const float4*)&hsh[w][0][grp][0];
                const float4 b0 = *(const float4*)&hsh[w][1][grp][0];
                const float4 a1 = *(const float4*)&hsh[w][0][grp][4];
                const float4 b1 = *(const float4*)&hsh[w][1][grp][4];
                const float2 a2 = *(const float2*)&hsh[w][0][grp][8];
                const float2 b2 = *(const float2*)&hsh[w][1][grp][8];
                hA[0] = pk2(a0.x, a0.y);  hB[0] = pk2(b0.x, b0.y);
                hA[1] = pk2(a0.z, a0.w);  hB[1] = pk2(b0.z, b0.w);
                hA[2] = pk2(a1.x, a1.y);  hB[2] = pk2(b1.x, b1.y);
                hA[3] = pk2(a1.z, a1.w);  hB[3] = pk2(b1.z, b1.w);
                hA[4] = pk2(a2.x, a2.y);  hB[4] = pk2(b2.x, b2.y);
            }
            w ^= 1;

            // ---- fc head, both streams ----
            ull yA2 = fma2(hA[0], fc2[0], fb2);
            ull yB2 = fma2(hB[0], fc2[0], fb2);
#pragma unroll
            for (int p = 1; p < 5; ++p) {
                yA2 = fma2(hA[p], fc2[p], yA2);
                yB2 = fma2(hB[p], fc2[p], yB2);
            }
            float alo, ahi, blo, bhi;
            upk2(yA2, alo, ahi);
            upk2(yB2, blo, bhi);

            if (liveA && j == 0) *opA = alo + ahi;
            if (liveB && j == 0) *opB = blo + bhi;
            opA += B;
            opB += B;
        }
    }
}

extern "C" void kernel_launch(void* const* d_in, const int* in_sizes, int n_in,
                              void* d_out, int out_size)
{
    const float* x    = (const float*)d_in[0];
    const float* w_ih = (const float*)d_in[1];
    const float* w_hh = (const float*)d_in[2];
    const float* b_ih = (const float*)d_in[3];
    const float* b_hh = (const float*)d_in[4];
    const float* fc_w = (const float*)d_in[5];
    const float* fc_b = (const float*)d_in[6];
    float* out = (float*)d_out;

    const int B = 4096;
    const int S = in_sizes[0] / B;   // 2048

    const int blocks = (B + 5) / 6;  // 683 one-warp blocks, 6 elems each

    lstm_dual2_kernel<<<blocks, 32>>>(x, w_ih, w_hh, b_ih, b_hh,
                                      fc_w, fc_b, out, S, B);
}